// round 2
// baseline (speedup 1.0000x reference)
#include <cuda_runtime.h>
#include <math.h>

#define Nn 4096
#define Dd 256
#define Kk 2048
#define MAXD 128
#define EPSc 1e-5f

// ---------------- scratch (device globals; no allocation) ----------------
__device__ float d_HN[Nn * Dd];       // normalized h
__device__ float d_psum[64 * Dd];
__device__ float d_psq[64 * Dd];
__device__ float d_mu[Dd];
__device__ float d_inv[Dd];           // gamma / sqrt(var+eps)
__device__ int   d_nbr[Nn * MAXD];    // CSR neighbor lists (sorted ascending)
__device__ int   d_ncnt[Nn];
__device__ float d_deg[Nn];
__device__ float d_Z1[Nn];
__device__ float d_Z3[Nn];
__device__ float d_PF[Nn];
__device__ float d_SC[Nn];            // scores
__device__ int   d_idx[Kk];
__device__ int   d_pos[Nn];           // inverse map: node -> rank, or -1
__device__ float d_sm[2];             // softmax max, sumexp
__device__ float d_rinv[Kk];          // 1 / rowcount(r) for the column-broadcast normalize

// ---------------- K1: column stats (deterministic 2-stage) ----------------
__global__ void k_colstats(const float* __restrict__ h) {
    int b = blockIdx.x, d = threadIdx.x;
    float s = 0.f, q = 0.f;
    int r0 = b * 64;
    for (int r = 0; r < 64; r++) {
        float v = h[(r0 + r) * Dd + d];
        s += v; q += v * v;
    }
    d_psum[b * Dd + d] = s;
    d_psq [b * Dd + d] = q;
}

__global__ void k_colfin(const float* __restrict__ gamma) {
    int d = threadIdx.x;
    float s = 0.f, q = 0.f;
    for (int b = 0; b < 64; b++) { s += d_psum[b * Dd + d]; q += d_psq[b * Dd + d]; }
    float mu  = s / (float)Nn;
    float var = q / (float)Nn - mu * mu;
    d_mu[d]  = mu;
    d_inv[d] = gamma[d] / sqrtf(var + EPSc);
}

// ---------------- K2: normalize h ----------------
__global__ void k_norm(const float* __restrict__ h, const float* __restrict__ beta) {
    int t = blockIdx.x * blockDim.x + threadIdx.x;
    if (t < Nn * Dd) {
        int d = t & (Dd - 1);
        d_HN[t] = (h[t] - d_mu[d]) * d_inv[d] + beta[d];
    }
}

// ---------------- K3: build CSR from dense g (warp per row; ordered, deterministic) --------
__global__ void k_csr(const float* __restrict__ g) {
    int warp = (blockIdx.x * blockDim.x + threadIdx.x) >> 5;
    int lane = threadIdx.x & 31;
    if (warp >= Nn) return;
    const float* row = g + (size_t)warp * Nn;
    int cnt = 0;
    float sumv = 0.f;
    for (int base = 0; base < Nn; base += 32) {
        float v = row[base + lane];
        unsigned m = __ballot_sync(0xffffffffu, v != 0.f);
        if (v != 0.f) {
            int p = cnt + __popc(m & ((1u << lane) - 1u));
            if (p < MAXD) d_nbr[warp * MAXD + p] = base + lane;
        }
        cnt += __popc(m);
        sumv += v;
    }
    for (int o = 16; o; o >>= 1) sumv += __shfl_down_sync(0xffffffffu, sumv, o);
    if (lane == 0) {
        d_ncnt[warp] = cnt < MAXD ? cnt : MAXD;
        d_deg[warp]  = sumv;
    }
}

// ---------------- K4: per-row agg, Z1, Z3, pf ----------------
__global__ void k_rowfeat(const float* __restrict__ wproj, const float* __restrict__ bproj) {
    int i = blockIdx.x, d = threadIdx.x;
    __shared__ int   snb[MAXD];
    __shared__ float red[Dd];
    __shared__ float res0, res1;
    int cnt = d_ncnt[i];
    if (d < cnt) snb[d] = d_nbr[i * MAXD + d];
    __syncthreads();
    float acc = 0.f;
    for (int e = 0; e < cnt; e++) acc += d_HN[snb[e] * Dd + d];
    float agg = acc / d_deg[i];
    float hv  = d_HN[i * Dd + d];
    float w   = wproj[d];

    red[d] = fabsf(hv - agg); __syncthreads();
    for (int s = 128; s > 0; s >>= 1) { if (d < s) red[d] += red[d + s]; __syncthreads(); }
    if (d == 0) res0 = red[0];
    __syncthreads();

    red[d] = agg * w; __syncthreads();
    for (int s = 128; s > 0; s >>= 1) { if (d < s) red[d] += red[d + s]; __syncthreads(); }
    if (d == 0) res1 = red[0];
    __syncthreads();

    red[d] = hv * w; __syncthreads();
    for (int s = 128; s > 0; s >>= 1) { if (d < s) red[d] += red[d + s]; __syncthreads(); }
    if (d == 0) {
        float b = bproj[0];
        d_Z1[i] = res0;
        d_Z3[i] = res1 + b;
        d_PF[i] = 1.f / (1.f + expf(-(red[0] + b)));
    }
}

// ---------------- K5a: softmax reduction over Z3 ----------------
__global__ void k_softmax_red() {
    __shared__ float sh[1024];
    int t = threadIdx.x;
    float mx = -3.4e38f;
    for (int i = t; i < Nn; i += 1024) mx = fmaxf(mx, d_Z3[i]);
    sh[t] = mx; __syncthreads();
    for (int s = 512; s > 0; s >>= 1) { if (t < s) sh[t] = fmaxf(sh[t], sh[t + s]); __syncthreads(); }
    float M = sh[0]; __syncthreads();
    float sm = 0.f;
    for (int i = t; i < Nn; i += 1024) sm += expf(d_Z3[i] - M);
    sh[t] = sm; __syncthreads();
    for (int s = 512; s > 0; s >>= 1) { if (t < s) sh[t] += sh[t + s]; __syncthreads(); }
    if (t == 0) { d_sm[0] = M; d_sm[1] = sh[0]; }
}

// ---------------- K5b: final scores ----------------
__global__ void k_scores(const float* __restrict__ sigma1) {
    int i = blockIdx.x * blockDim.x + threadIdx.x;
    if (i >= Nn) return;
    float pg = expf(d_Z3[i] - d_sm[0]) / d_sm[1];
    float pl = 1.f / (1.f + expf(-(d_Z1[i] + d_deg[i])));
    float pt = 1.f / (1.f + expf(-(pl + pg)));
    float s1 = sigma1[0];
    d_SC[i] = s1 * pt + (1.f - s1) * d_PF[i];
}

// ---------------- K6: exact top-k via full bitonic sort (matches lax.top_k ordering) ------
__global__ void k_topk(float* __restrict__ out_idx) {
    __shared__ unsigned long long sk[Nn];
    int t = threadIdx.x;
    for (int i = t; i < Nn; i += 1024) {
        unsigned u = __float_as_uint(d_SC[i]);
        u = (u & 0x80000000u) ? ~u : (u | 0x80000000u);   // ascending-orderable
        sk[i] = ((unsigned long long)(~u) << 32) | (unsigned)i; // asc key = desc score, asc idx on ties
    }
    __syncthreads();
    for (int k = 2; k <= Nn; k <<= 1) {
        for (int j = k >> 1; j > 0; j >>= 1) {
            for (int i = t; i < Nn; i += 1024) {
                int ixj = i ^ j;
                if (ixj > i) {
                    bool up = ((i & k) == 0);
                    unsigned long long a = sk[i], b = sk[ixj];
                    if ((a > b) == up) { sk[i] = b; sk[ixj] = a; }
                }
            }
            __syncthreads();
        }
    }
    for (int i = t; i < Nn; i += 1024) d_pos[i] = -1;
    __syncthreads();
    for (int c = t; c < Kk; c += 1024) {
        int j = (int)(sk[c] & 0xffffffffULL);
        d_idx[c] = j;
        d_pos[j] = c;
        out_idx[c] = (float)j;
    }
}

// ---------------- K7: per-selected-row two-hop bitmap -> new_h + binary g_new + rowcount ----
__global__ void k_pool(float* __restrict__ out_gnew, float* __restrict__ out_newh) {
    __shared__ unsigned bm[Nn / 32];
    __shared__ int list[Nn];
    __shared__ int scnt;
    __shared__ int redi[256];
    int r = blockIdx.x, d = threadIdx.x;
    int i = d_idx[r];
    for (int w = d; w < Nn / 32; w += 256) bm[w] = 0u;
    if (d == 0) scnt = 0;
    __syncthreads();
    int c1 = d_ncnt[i];
    for (int e = d; e < c1; e += 256) {
        int k = d_nbr[i * MAXD + e];
        int c2 = d_ncnt[k];
        const int* nb = &d_nbr[k * MAXD];
        for (int f = 0; f < c2; f++) {
            int j = nb[f];
            atomicOr(&bm[j >> 5], 1u << (j & 31));
        }
    }
    __syncthreads();
    for (int w = d; w < Nn / 32; w += 256) {
        unsigned v = bm[w];
        while (v) {
            int b = __ffs((int)v) - 1;
            v &= v - 1;
            int p = atomicAdd(&scnt, 1);
            list[p] = w * 32 + b;
        }
    }
    __syncthreads();
    int m = scnt;

    // new_h[r] = sum_{j in twohop(i)} scores[j] * HN[j]  (thread d owns dim d; coalesced HN row loads)
    float acc = 0.f;
    for (int e = 0; e < m; e++) {
        int j = list[e];
        acc += d_SC[j] * d_HN[j * Dd + d];
    }
    out_newh[(size_t)r * Dd + d] = acc;

    // g_new row r (binary for now; column-broadcast normalize happens in K8)
    for (int c = d; c < Kk; c += 256) out_gnew[(size_t)r * Kk + c] = 0.f;
    int lc = 0;
    for (int e = d; e < m; e += 256) if (d_pos[list[e]] >= 0) lc++;
    redi[d] = lc; __syncthreads();
    for (int s = 128; s > 0; s >>= 1) { if (d < s) redi[d] += redi[d + s]; __syncthreads(); }
    if (d == 0) d_rinv[r] = 1.f / (float)redi[0];
    __syncthreads();
    for (int e = d; e < m; e += 256) {
        int c = d_pos[list[e]];
        if (c >= 0) out_gnew[(size_t)r * Kk + c] = 1.f;
    }
}

// ---------------- K8: replicate reference's last-axis broadcast: [r][c] /= rowsum(row c) ----
__global__ void k_gnorm(float* __restrict__ out_gnew) {
    size_t t = (size_t)blockIdx.x * blockDim.x + threadIdx.x;
    if (t < (size_t)Kk * Kk) {
        int c = (int)(t & (Kk - 1));
        out_gnew[t] *= d_rinv[c];
    }
}

// ---------------- launch ----------------
extern "C" void kernel_launch(void* const* d_in, const int* in_sizes, int n_in,
                              void* d_out, int out_size) {
    const float* g      = (const float*)d_in[0];
    const float* h      = (const float*)d_in[1];
    const float* gamma  = (const float*)d_in[2];
    const float* beta   = (const float*)d_in[3];
    const float* wproj  = (const float*)d_in[4];
    const float* bproj  = (const float*)d_in[5];
    const float* sigma1 = (const float*)d_in[6];

    float* out      = (float*)d_out;
    float* out_gnew = out;                               // Kk*Kk
    float* out_newh = out + (size_t)Kk * Kk;             // Kk*Dd
    float* out_idx  = out_newh + (size_t)Kk * Dd;        // Kk

    k_colstats   <<<64, 256>>>(h);
    k_colfin     <<<1, 256>>>(gamma);
    k_norm       <<<(Nn * Dd) / 256, 256>>>(h, beta);
    k_csr        <<<Nn / 8, 256>>>(g);
    k_rowfeat    <<<Nn, 256>>>(wproj, bproj);
    k_softmax_red<<<1, 1024>>>();
    k_scores     <<<Nn / 256, 256>>>(sigma1);
    k_topk       <<<1, 1024>>>(out_idx);
    k_pool       <<<Kk, 256>>>(out_gnew, out_newh);
    k_gnorm      <<<(Kk * Kk) / 256, 256>>>(out_gnew);
}

// round 4
// speedup vs baseline: 1.2755x; 1.2755x over previous
#include <cuda_runtime.h>
#include <math.h>

#define Nn 4096
#define Dd 256
#define Kk 2048
#define MAXD 128
#define EPSc 1e-5f

// ---------------- scratch (device globals; no allocation) ----------------
__device__ float d_HN[Nn * Dd];        // normalized h
__device__ float d_psum[64 * Dd];
__device__ float d_psq[64 * Dd];
__device__ float d_mu[Dd];
__device__ float d_inv[Dd];            // gamma / sqrt(var+eps)
__device__ int   d_nbr[Nn * MAXD];     // CSR neighbor lists
__device__ int   d_ncnt[Nn];
__device__ float d_deg[Nn];
__device__ float d_Z1[Nn];
__device__ float d_Z3[Nn];
__device__ float d_PF[Nn];
__device__ float d_SC[Nn];             // scores
__device__ int   d_idx[Kk];
__device__ unsigned d_selw[Nn / 32];   // bitmask of selected nodes
__device__ unsigned d_bm[Kk * (Nn / 32)]; // per-selected-row two-hop bitmaps (1 MB)
__device__ float d_rinv[Kk];           // 1 / rowcount(r)

// ---------------- K1: column stats (deterministic 2-stage) ----------------
__global__ void k_colstats(const float* __restrict__ h) {
    int b = blockIdx.x, d = threadIdx.x;
    float s = 0.f, q = 0.f;
    int r0 = b * 64;
    for (int r = 0; r < 64; r++) {
        float v = h[(r0 + r) * Dd + d];
        s += v; q += v * v;
    }
    d_psum[b * Dd + d] = s;
    d_psq [b * Dd + d] = q;
}

__global__ void k_colfin(const float* __restrict__ gamma) {
    int d = threadIdx.x;
    float s = 0.f, q = 0.f;
    for (int b = 0; b < 64; b++) { s += d_psum[b * Dd + d]; q += d_psq[b * Dd + d]; }
    float mu  = s / (float)Nn;
    float var = q / (float)Nn - mu * mu;
    d_mu[d]  = mu;
    d_inv[d] = gamma[d] / sqrtf(var + EPSc);
}

// ---------------- K2: normalize h (float4) ----------------
__global__ void k_norm(const float* __restrict__ h, const float* __restrict__ beta) {
    int t = blockIdx.x * blockDim.x + threadIdx.x;          // over Nn*Dd/4
    int d4 = t & (Dd / 4 - 1);
    float4 hv = ((const float4*)h)[t];
    float4 mu = ((const float4*)d_mu)[d4];
    float4 iv = ((const float4*)d_inv)[d4];
    float4 be = ((const float4*)beta)[d4];
    float4 o;
    o.x = (hv.x - mu.x) * iv.x + be.x;
    o.y = (hv.y - mu.y) * iv.y + be.y;
    o.z = (hv.z - mu.z) * iv.z + be.z;
    o.w = (hv.w - mu.w) * iv.w + be.w;
    ((float4*)d_HN)[t] = o;
}

// ---------------- K3: build CSR from dense g (warp/row, float4 loads) ----------------
__global__ void k_csr(const float* __restrict__ g) {
    int warp = (blockIdx.x * blockDim.x + threadIdx.x) >> 5;
    int lane = threadIdx.x & 31;
    if (warp >= Nn) return;
    const float4* row = (const float4*)(g + (size_t)warp * Nn);
    int cnt = 0;
    float sumv = 0.f;
    unsigned lmask = (1u << lane) - 1u;
    for (int b = 0; b < 32; b++) {
        float4 v = row[b * 32 + lane];
        sumv += v.x + v.y + v.z + v.w;
        int base = b * 128 + lane * 4;
        unsigned m;
        m = __ballot_sync(0xffffffffu, v.x != 0.f);
        if (v.x != 0.f) { int p = cnt + __popc(m & lmask); if (p < MAXD) d_nbr[warp * MAXD + p] = base + 0; }
        cnt += __popc(m);
        m = __ballot_sync(0xffffffffu, v.y != 0.f);
        if (v.y != 0.f) { int p = cnt + __popc(m & lmask); if (p < MAXD) d_nbr[warp * MAXD + p] = base + 1; }
        cnt += __popc(m);
        m = __ballot_sync(0xffffffffu, v.z != 0.f);
        if (v.z != 0.f) { int p = cnt + __popc(m & lmask); if (p < MAXD) d_nbr[warp * MAXD + p] = base + 2; }
        cnt += __popc(m);
        m = __ballot_sync(0xffffffffu, v.w != 0.f);
        if (v.w != 0.f) { int p = cnt + __popc(m & lmask); if (p < MAXD) d_nbr[warp * MAXD + p] = base + 3; }
        cnt += __popc(m);
    }
    for (int o = 16; o; o >>= 1) sumv += __shfl_down_sync(0xffffffffu, sumv, o);
    if (lane == 0) {
        d_ncnt[warp] = cnt < MAXD ? cnt : MAXD;
        d_deg[warp]  = sumv;
    }
}

// ---------------- K4: per-row agg, Z1, Z3, pf (single fused 3-value reduction) ----------
__global__ void k_rowfeat(const float* __restrict__ wproj, const float* __restrict__ bproj) {
    int i = blockIdx.x, d = threadIdx.x;
    __shared__ int   snb[MAXD];
    __shared__ float wr[8][3];
    int cnt = d_ncnt[i];
    if (d < cnt) snb[d] = d_nbr[i * MAXD + d];
    __syncthreads();
    float acc = 0.f;
    for (int e = 0; e < cnt; e++) acc += d_HN[snb[e] * Dd + d];
    float agg = acc / d_deg[i];
    float hv  = d_HN[i * Dd + d];
    float w   = wproj[d];
    float a = fabsf(hv - agg), b = agg * w, c = hv * w;
    for (int o = 16; o; o >>= 1) {
        a += __shfl_down_sync(0xffffffffu, a, o);
        b += __shfl_down_sync(0xffffffffu, b, o);
        c += __shfl_down_sync(0xffffffffu, c, o);
    }
    if ((d & 31) == 0) { wr[d >> 5][0] = a; wr[d >> 5][1] = b; wr[d >> 5][2] = c; }
    __syncthreads();
    if (d == 0) {
        float A = 0.f, B = 0.f, C = 0.f;
        for (int k = 0; k < 8; k++) { A += wr[k][0]; B += wr[k][1]; C += wr[k][2]; }
        float bb = bproj[0];
        d_Z1[i] = A;
        d_Z3[i] = B + bb;
        d_PF[i] = 1.f / (1.f + expf(-(C + bb)));
    }
}

// ---------------- K5: fused softmax + scores + exact top-k bitonic sort ----------------
__global__ void k_topk(const float* __restrict__ sigma1, float* __restrict__ out_idx) {
    __shared__ unsigned long long sk[Nn];
    __shared__ float sh[1024];
    int t = threadIdx.x;

    // softmax(Z3) reduction
    float mx = -3.4e38f;
    for (int i = t; i < Nn; i += 1024) mx = fmaxf(mx, d_Z3[i]);
    sh[t] = mx; __syncthreads();
    for (int s = 512; s > 0; s >>= 1) { if (t < s) sh[t] = fmaxf(sh[t], sh[t + s]); __syncthreads(); }
    float M = sh[0]; __syncthreads();
    float sm = 0.f;
    for (int i = t; i < Nn; i += 1024) sm += expf(d_Z3[i] - M);
    sh[t] = sm; __syncthreads();
    for (int s = 512; s > 0; s >>= 1) { if (t < s) sh[t] += sh[t + s]; __syncthreads(); }
    float S = sh[0];
    float s1 = sigma1[0];

    // scores + sort keys
    for (int i = t; i < Nn; i += 1024) {
        float pg = expf(d_Z3[i] - M) / S;
        float pl = 1.f / (1.f + expf(-(d_Z1[i] + d_deg[i])));
        float pt = 1.f / (1.f + expf(-(pl + pg)));
        float sc = s1 * pt + (1.f - s1) * d_PF[i];
        d_SC[i] = sc;
        unsigned u = __float_as_uint(sc);
        u = (u & 0x80000000u) ? ~u : (u | 0x80000000u);
        sk[i] = ((unsigned long long)(~u) << 32) | (unsigned)i;  // asc key = desc score, asc idx ties
    }
    if (t < Nn / 32) d_selw[t] = 0u;
    __syncthreads();

    for (int k = 2; k <= Nn; k <<= 1) {
        for (int j = k >> 1; j > 0; j >>= 1) {
            for (int i = t; i < Nn; i += 1024) {
                int ixj = i ^ j;
                if (ixj > i) {
                    bool up = ((i & k) == 0);
                    unsigned long long a = sk[i], b = sk[ixj];
                    if ((a > b) == up) { sk[i] = b; sk[ixj] = a; }
                }
            }
            __syncthreads();
        }
    }
    for (int c = t; c < Kk; c += 1024) {
        int j = (int)(sk[c] & 0xffffffffULL);
        d_idx[c] = j;
        atomicOr(&d_selw[j >> 5], 1u << (j & 31));
        out_idx[c] = (float)j;
    }
}

// ---------------- K6: per-selected-row two-hop -> new_h, bitmap, rowcount ----------------
__global__ void k_pool(float* __restrict__ out_newh) {
    __shared__ unsigned bm[Nn / 32];
    __shared__ int scn[Nn / 32];
    __shared__ int list[Nn];
    __shared__ float4 red[3][64];
    __shared__ int redi[256];
    int r = blockIdx.x, d = threadIdx.x;
    int i = d_idx[r];
    if (d < Nn / 32) bm[d] = 0u;
    __syncthreads();

    // two-hop expansion into bitmap
    int c1 = d_ncnt[i];
    for (int e = d; e < c1; e += 256) {
        int k = d_nbr[i * MAXD + e];
        int c2 = d_ncnt[k];
        const int* nb = &d_nbr[k * MAXD];
        for (int f = 0; f < c2; f++) {
            int j = nb[f];
            atomicOr(&bm[j >> 5], 1u << (j & 31));
        }
    }
    __syncthreads();

    // deterministic ordered extraction via prefix scan over 128 words
    int pc = (d < Nn / 32) ? __popc(bm[d]) : 0;
    if (d < Nn / 32) scn[d] = pc;
    __syncthreads();
    for (int off = 1; off < Nn / 32; off <<= 1) {
        int v = 0;
        if (d < Nn / 32) { v = scn[d]; if (d >= off) v += scn[d - off]; }
        __syncthreads();
        if (d < Nn / 32) scn[d] = v;
        __syncthreads();
    }
    if (d < Nn / 32) {
        int p = scn[d] - pc;
        unsigned v = bm[d];
        while (v) { int b = __ffs((int)v) - 1; v &= v - 1; list[p++] = d * 32 + b; }
        d_bm[r * (Nn / 32) + d] = bm[d];           // persist bitmap for k_gnew
    }
    // selected-in-row count -> rinv
    int csel = (d < Nn / 32) ? __popc(bm[d] & d_selw[d]) : 0;
    redi[d] = csel;
    __syncthreads();
    int m = scn[Nn / 32 - 1];
    for (int s = 128; s > 0; s >>= 1) { if (d < s) redi[d] += redi[d + s]; __syncthreads(); }
    if (d == 0) d_rinv[r] = 1.f / (float)redi[0];

    // new_h[r] = sum_j SC[j]*HN[j] ; 4 groups x 64 lanes, float4, 4 indep chains
    int grp = d >> 6, l = d & 63;
    const float4* HN4 = (const float4*)d_HN;
    float4 acc = make_float4(0.f, 0.f, 0.f, 0.f);
    for (int e = grp; e < m; e += 4) {
        int j = list[e];
        float s = d_SC[j];
        float4 v = HN4[j * 64 + l];
        acc.x += s * v.x; acc.y += s * v.y; acc.z += s * v.z; acc.w += s * v.w;
    }
    if (grp > 0) red[grp - 1][l] = acc;
    __syncthreads();
    if (grp == 0) {
        for (int k = 0; k < 3; k++) {
            float4 v = red[k][l];
            acc.x += v.x; acc.y += v.y; acc.z += v.z; acc.w += v.w;
        }
        ((float4*)out_newh)[(size_t)r * 64 + l] = acc;
    }
}

// ---------------- K7: write g_new directly (membership bit * column rinv) ----------------
__global__ void k_gnew(float* __restrict__ out_gnew) {
    int t = blockIdx.x * blockDim.x + threadIdx.x;
    int r = t >> 11, c = t & (Kk - 1);
    int j = d_idx[c];
    unsigned w = d_bm[r * (Nn / 32) + (j >> 5)];
    out_gnew[t] = ((w >> (j & 31)) & 1u) ? d_rinv[c] : 0.f;
}

// ---------------- launch ----------------
extern "C" void kernel_launch(void* const* d_in, const int* in_sizes, int n_in,
                              void* d_out, int out_size) {
    const float* g      = (const float*)d_in[0];
    const float* h      = (const float*)d_in[1];
    const float* gamma  = (const float*)d_in[2];
    const float* beta   = (const float*)d_in[3];
    const float* wproj  = (const float*)d_in[4];
    const float* bproj  = (const float*)d_in[5];
    const float* sigma1 = (const float*)d_in[6];

    float* out      = (float*)d_out;
    float* out_gnew = out;                               // Kk*Kk
    float* out_newh = out + (size_t)Kk * Kk;             // Kk*Dd
    float* out_idx  = out_newh + (size_t)Kk * Dd;        // Kk

    k_colstats<<<64, 256>>>(h);
    k_colfin  <<<1, 256>>>(gamma);
    k_norm    <<<(Nn * Dd / 4) / 256, 256>>>(h, beta);
    k_csr     <<<Nn / 8, 256>>>(g);
    k_rowfeat <<<Nn, 256>>>(wproj, bproj);
    k_topk    <<<1, 1024>>>(sigma1, out_idx);
    k_pool    <<<Kk, 256>>>(out_newh);
    k_gnew    <<<(Kk * Kk) / 256, 256>>>(out_gnew);
}